// round 1
// baseline (speedup 1.0000x reference)
#include <cuda_runtime.h>
#include <cstddef>

// ---------------- problem constants ----------------
#define BATCH 2
#define C_DIM 256
#define HW 96
#define PIX (HW*HW)          // 9216
#define INNER 14
#define NFEAT (INNER*18)     // 252
#define NTOK PIX             // 9216

// ---------------- device scratch (no cudaMalloc allowed) ----------------
__device__ float g_fmap [BATCH * C_DIM * PIX];            // (b,c,p)
__device__ float g_xr   [BATCH * INNER * PIX];            // (b,c,p)
__device__ float g_conv [3 * BATCH * INNER * PIX];        // (i,b,c,p)
__device__ float g_feats[BATCH * NFEAT * PIX];            // (b,f,p)
__device__ float g_tokT [BATCH * C_DIM * PIX];            // (b,c,p) fused
__device__ float g_tok  [BATCH * NTOK * C_DIM];           // (b,p,c)
__device__ float g_scores[(size_t)BATCH * NTOK * NTOK];   // (b,n,m)  ~680MB
__device__ float g_att  [BATCH * NTOK * C_DIM];           // (b,p,c)

// ---------------- GEMM: C = alpha * A * op(B) + bias ----------------
// A: M x K row-major (lda).  TB=false: B is K x Np (ldb). TB=true: B is Np x K (ldb).
// BM=BN=128, BK=8, 256 threads, 8x8 per-thread microtile.
template<bool TB>
__global__ __launch_bounds__(256)
void gemm128(const float* __restrict__ A, const float* __restrict__ Bm,
             float* __restrict__ Cm,
             int M, int Np, int K, int lda, int ldb, int ldc,
             float alpha, const float* __restrict__ bias,
             size_t sA, size_t sB, size_t sC)
{
    __shared__ float As[8][132];
    __shared__ float Bs[8][132];

    int bz = blockIdx.z;
    A  += (size_t)bz * sA;
    Bm += (size_t)bz * sB;
    Cm += (size_t)bz * sC;

    int tid = threadIdx.x;
    int tx = tid % 16;      // col group
    int ty = tid / 16;      // row group
    int row0 = blockIdx.y * 128;
    int col0 = blockIdx.x * 128;

    float acc[8][8];
    #pragma unroll
    for (int i = 0; i < 8; i++)
        #pragma unroll
        for (int j = 0; j < 8; j++) acc[i][j] = 0.f;

    // A tile load mapping: k = tid%8, 4 consecutive rows per thread
    int a_k = tid % 8;
    int a_m = (tid / 8) * 4;

    for (int k0 = 0; k0 < K; k0 += 8) {
        #pragma unroll
        for (int j = 0; j < 4; j++) {
            int m = a_m + j;
            int kk = k0 + a_k;
            float v = 0.f;
            if (row0 + m < M && kk < K) v = A[(size_t)(row0 + m) * lda + kk];
            As[a_k][m] = v;
        }
        if (!TB) {
            int b_n  = tid % 128;
            int b_kb = (tid / 128) * 4;
            #pragma unroll
            for (int j = 0; j < 4; j++) {
                int kk = k0 + b_kb + j;
                float v = 0.f;
                if (kk < K && col0 + b_n < Np) v = Bm[(size_t)kk * ldb + col0 + b_n];
                Bs[b_kb + j][b_n] = v;
            }
        } else {
            int b_k  = tid % 8;
            int b_nb = (tid / 8) * 4;
            #pragma unroll
            for (int j = 0; j < 4; j++) {
                int n = b_nb + j;
                int kk = k0 + b_k;
                float v = 0.f;
                if (kk < K && col0 + n < Np) v = Bm[(size_t)(col0 + n) * ldb + kk];
                Bs[b_k][n] = v;
            }
        }
        __syncthreads();

        #pragma unroll
        for (int kk = 0; kk < 8; kk++) {
            float a[8], b[8];
            #pragma unroll
            for (int i = 0; i < 8; i++) a[i] = As[kk][ty * 8 + i];
            #pragma unroll
            for (int j = 0; j < 8; j++) b[j] = Bs[kk][tx * 8 + j];
            #pragma unroll
            for (int i = 0; i < 8; i++)
                #pragma unroll
                for (int j = 0; j < 8; j++)
                    acc[i][j] += a[i] * b[j];
        }
        __syncthreads();
    }

    #pragma unroll
    for (int i = 0; i < 8; i++) {
        int m = row0 + ty * 8 + i;
        if (m >= M) continue;
        float bv = bias ? bias[m] : 0.f;
        #pragma unroll
        for (int j = 0; j < 8; j++) {
            int n = col0 + tx * 8 + j;
            if (n < Np) Cm[(size_t)m * ldc + n] = alpha * acc[i][j] + bv;
        }
    }
}

// ---------------- reduce: xr = reduce_w(14x256) @ fmap + b ----------------
__global__ __launch_bounds__(256)
void reduce_kernel(const float* __restrict__ fmap, const float* __restrict__ w,
                   const float* __restrict__ bias, float* __restrict__ xr)
{
    __shared__ float ws[INNER * C_DIM];
    int tid = threadIdx.x;
    for (int i = tid; i < INNER * C_DIM; i += 256) ws[i] = w[i];
    __syncthreads();

    int b = blockIdx.y;
    int p = blockIdx.x * 256 + tid;
    const float* fin = fmap + (size_t)b * C_DIM * PIX;
    float acc[INNER];
    #pragma unroll
    for (int o = 0; o < INNER; o++) acc[o] = 0.f;
    for (int ci = 0; ci < C_DIM; ci++) {
        float v = fin[(size_t)ci * PIX + p];
        #pragma unroll
        for (int o = 0; o < INNER; o++) acc[o] += ws[o * C_DIM + ci] * v;
    }
    float* xo = xr + (size_t)b * INNER * PIX;
    #pragma unroll
    for (int o = 0; o < INNER; o++) xo[(size_t)o * PIX + p] = acc[o] + bias[o];
}

// ---------------- dilated 3x3 conv (pad=d, dil=d), 14->14 ----------------
__global__ __launch_bounds__(256)
void dilconv_kernel(const float* __restrict__ xr, const float* __restrict__ dw,
                    const float* __restrict__ db, float* __restrict__ conv)
{
    __shared__ float ws[INNER * INNER * 9];
    int i = blockIdx.z;           // dilation index 0..2
    int d = i + 1;
    int b = blockIdx.y;
    int tid = threadIdx.x;
    for (int k = tid; k < INNER * INNER * 9; k += 256)
        ws[k] = dw[(size_t)i * INNER * INNER * 9 + k];
    __syncthreads();

    int p = blockIdx.x * 256 + tid;
    int h = p / HW, w = p % HW;
    const float* xin = xr + (size_t)b * INNER * PIX;
    float acc[INNER];
    #pragma unroll
    for (int co = 0; co < INNER; co++) acc[co] = 0.f;

    #pragma unroll
    for (int kh = 0; kh < 3; kh++) {
        int hh = h + (kh - 1) * d;
        if (hh < 0 || hh >= HW) continue;
        #pragma unroll
        for (int kw = 0; kw < 3; kw++) {
            int ww = w + (kw - 1) * d;
            if (ww < 0 || ww >= HW) continue;
            int q = hh * HW + ww;
            for (int ci = 0; ci < INNER; ci++) {
                float v = xin[(size_t)ci * PIX + q];
                int widx = ci * 9 + kh * 3 + kw;
                #pragma unroll
                for (int co = 0; co < INNER; co++)
                    acc[co] += ws[co * (INNER * 9) + widx] * v;
            }
        }
    }
    float* cout = conv + ((size_t)(i * BATCH + b) * INNER) * PIX;
    #pragma unroll
    for (int co = 0; co < INNER; co++)
        cout[(size_t)co * PIX + p] = acc[co] + db[i * INNER + co];
}

// ---------------- feats[(i*6+t)*14+c][p] = conv_i[c][p] * tf_t[c][p] ----------------
__global__ __launch_bounds__(256)
void feats_kernel(const float* __restrict__ xr, const float* __restrict__ conv,
                  float* __restrict__ feats)
{
    int b = blockIdx.y;
    int p = blockIdx.x * 256 + threadIdx.x;
    int h = p / HW, w = p % HW;
    const float* xin = xr + (size_t)b * INNER * PIX;
    float* fo = feats + (size_t)b * NFEAT * PIX;

    int q[6];
    q[0] = p;                               // identity
    q[1] = h * HW + (HW - 1 - w);           // flip W
    q[2] = (HW - 1 - h) * HW + w;           // flip H
    q[3] = w * HW + (HW - 1 - h);           // rot90 k=1
    q[4] = (HW - 1 - h) * HW + (HW - 1 - w);// rot180
    q[5] = (HW - 1 - w) * HW + h;           // rot270

    for (int c = 0; c < INNER; c++) {
        float cv[3];
        #pragma unroll
        for (int i = 0; i < 3; i++)
            cv[i] = conv[((size_t)(i * BATCH + b) * INNER + c) * PIX + p];
        float tv[6];
        #pragma unroll
        for (int t = 0; t < 6; t++)
            tv[t] = xin[(size_t)c * PIX + q[t]];
        #pragma unroll
        for (int i = 0; i < 3; i++)
            #pragma unroll
            for (int t = 0; t < 6; t++)
                fo[((size_t)((i * 6 + t) * INNER + c)) * PIX + p] = cv[i] * tv[t];
    }
}

// ---------------- transpose (b,c,p) -> (b,p,c) ----------------
__global__ __launch_bounds__(256)
void transpose_kernel(const float* __restrict__ src, float* __restrict__ dst)
{
    __shared__ float tile[32][33];
    int b = blockIdx.z;
    int p0 = blockIdx.x * 32, c0 = blockIdx.y * 32;
    const float* s = src + (size_t)b * C_DIM * PIX;
    float* d = dst + (size_t)b * NTOK * C_DIM;
    int tx = threadIdx.x, ty = threadIdx.y;
    #pragma unroll
    for (int j = 0; j < 32; j += 8)
        tile[ty + j][tx] = s[(size_t)(c0 + ty + j) * PIX + p0 + tx];
    __syncthreads();
    #pragma unroll
    for (int j = 0; j < 32; j += 8)
        d[(size_t)(p0 + ty + j) * C_DIM + c0 + tx] = tile[tx][ty + j];
}

// ---------------- row softmax over 9216 entries, row kept in smem ----------------
__global__ __launch_bounds__(256)
void softmax_kernel(float* __restrict__ S)
{
    __shared__ float buf[NTOK];
    __shared__ float red[256];
    size_t base = ((size_t)blockIdx.y * NTOK + blockIdx.x) * NTOK;
    float* row = S + base;
    int tid = threadIdx.x;

    float mx = -1e30f;
    for (int i = tid; i < NTOK; i += 256) { float v = row[i]; buf[i] = v; mx = fmaxf(mx, v); }
    red[tid] = mx; __syncthreads();
    for (int s = 128; s > 0; s >>= 1) { if (tid < s) red[tid] = fmaxf(red[tid], red[tid + s]); __syncthreads(); }
    mx = red[0];
    __syncthreads();

    float sum = 0.f;
    for (int i = tid; i < NTOK; i += 256) { float e = __expf(buf[i] - mx); buf[i] = e; sum += e; }
    red[tid] = sum; __syncthreads();
    for (int s = 128; s > 0; s >>= 1) { if (tid < s) red[tid] += red[tid + s]; __syncthreads(); }
    float inv = 1.f / red[0];

    for (int i = tid; i < NTOK; i += 256) row[i] = buf[i] * inv;
}

// ---------------- final: out(b,c,p) = fmap + 0.2 * att(b,p,c)^T ----------------
__global__ __launch_bounds__(256)
void final_kernel(const float* __restrict__ fmap, const float* __restrict__ att,
                  float* __restrict__ out)
{
    __shared__ float tile[32][33];
    int b = blockIdx.z;
    int p0 = blockIdx.x * 32, c0 = blockIdx.y * 32;
    int tx = threadIdx.x, ty = threadIdx.y;
    const float* a = att + (size_t)b * NTOK * C_DIM;
    #pragma unroll
    for (int j = 0; j < 32; j += 8)
        tile[ty + j][tx] = a[(size_t)(p0 + ty + j) * C_DIM + c0 + tx];
    __syncthreads();
    const float* f = fmap + (size_t)b * C_DIM * PIX;
    float* o = out + (size_t)b * C_DIM * PIX;
    #pragma unroll
    for (int j = 0; j < 32; j += 8) {
        int c = c0 + ty + j, p = p0 + tx;
        o[(size_t)c * PIX + p] = f[(size_t)c * PIX + p] + 0.2f * tile[tx][ty + j];
    }
}

// ---------------- launch ----------------
extern "C" void kernel_launch(void* const* d_in, const int* in_sizes, int n_in,
                              void* d_out, int out_size)
{
    const float* x        = (const float*)d_in[0];
    const float* proj_w   = (const float*)d_in[1];
    const float* proj_b   = (const float*)d_in[2];
    const float* reduce_w = (const float*)d_in[3];
    const float* reduce_b = (const float*)d_in[4];
    const float* dil_w    = (const float*)d_in[5];
    const float* dil_b    = (const float*)d_in[6];
    const float* fuse_w   = (const float*)d_in[7];
    const float* fuse_b   = (const float*)d_in[8];
    float* out = (float*)d_out;

    void *p_fmap, *p_xr, *p_conv, *p_feats, *p_tokT, *p_tok, *p_scores, *p_att;
    cudaGetSymbolAddress(&p_fmap,   g_fmap);
    cudaGetSymbolAddress(&p_xr,     g_xr);
    cudaGetSymbolAddress(&p_conv,   g_conv);
    cudaGetSymbolAddress(&p_feats,  g_feats);
    cudaGetSymbolAddress(&p_tokT,   g_tokT);
    cudaGetSymbolAddress(&p_tok,    g_tok);
    cudaGetSymbolAddress(&p_scores, g_scores);
    cudaGetSymbolAddress(&p_att,    g_att);

    float* fmap   = (float*)p_fmap;
    float* xr     = (float*)p_xr;
    float* conv   = (float*)p_conv;
    float* feats  = (float*)p_feats;
    float* tokT   = (float*)p_tokT;
    float* tok    = (float*)p_tok;
    float* scores = (float*)p_scores;
    float* att    = (float*)p_att;

    // 1) proj 1x1: fmap[b] = proj_w(256x256) @ x[b](256xP) + proj_b
    gemm128<false><<<dim3(PIX/128, C_DIM/128, BATCH), 256>>>(
        proj_w, x, fmap, C_DIM, PIX, C_DIM, C_DIM, PIX, PIX,
        1.f, proj_b, 0, (size_t)C_DIM*PIX, (size_t)C_DIM*PIX);

    // 2) reduce 1x1: xr = reduce_w(14x256) @ fmap + reduce_b
    reduce_kernel<<<dim3(PIX/256, BATCH), 256>>>(fmap, reduce_w, reduce_b, xr);

    // 3) dilated convs (d = 1,2,3)
    dilconv_kernel<<<dim3(PIX/256, BATCH, 3), 256>>>(xr, dil_w, dil_b, conv);

    // 4) feats = conv_i * tf_t
    feats_kernel<<<dim3(PIX/256, BATCH), 256>>>(xr, conv, feats);

    // 5) fuse 1x1: tokT[b] = fuse_w(256x252) @ feats[b] + fuse_b
    gemm128<false><<<dim3(PIX/128, C_DIM/128, BATCH), 256>>>(
        fuse_w, feats, tokT, C_DIM, PIX, NFEAT, NFEAT, PIX, PIX,
        1.f, fuse_b, 0, (size_t)NFEAT*PIX, (size_t)C_DIM*PIX);

    // 6) transpose -> tok (b,p,c)
    transpose_kernel<<<dim3(PIX/32, C_DIM/32, BATCH), dim3(32, 8)>>>(tokT, tok);

    // 7) scores = (tok @ tok^T) / sqrt(C)
    gemm128<true><<<dim3(NTOK/128, NTOK/128, BATCH), 256>>>(
        tok, tok, scores, NTOK, NTOK, C_DIM, C_DIM, C_DIM, NTOK,
        0.0625f, nullptr, (size_t)NTOK*C_DIM, (size_t)NTOK*C_DIM, (size_t)NTOK*NTOK);

    // 8) row softmax
    softmax_kernel<<<dim3(NTOK, BATCH), 256>>>(scores);

    // 9) att = scores @ tok
    gemm128<false><<<dim3(C_DIM/128, NTOK/128, BATCH), 256>>>(
        scores, tok, att, NTOK, C_DIM, NTOK, NTOK, C_DIM, C_DIM,
        1.f, nullptr, (size_t)NTOK*NTOK, (size_t)NTOK*C_DIM, (size_t)NTOK*C_DIM);

    // 10) out = fmap + 0.2 * att^T
    final_kernel<<<dim3(PIX/32, C_DIM/32, BATCH), dim3(32, 8)>>>(fmap, att, out);
}

// round 2
// speedup vs baseline: 2.8755x; 2.8755x over previous
#include <cuda_runtime.h>
#include <cstdint>
#include <cstddef>

// ---------------- problem constants ----------------
#define BATCH 2
#define C_DIM 256
#define HW 96
#define PIX (HW*HW)          // 9216
#define INNER 14
#define NFEAT (INNER*18)     // 252
#define NTOK PIX             // 9216

// ---------------- device scratch ----------------
__device__ float g_fmap [BATCH * C_DIM * PIX];
__device__ float g_xr   [BATCH * INNER * PIX];
__device__ float g_conv [3 * BATCH * INNER * PIX];
__device__ float g_feats[BATCH * NFEAT * PIX];
__device__ float g_tokT [BATCH * C_DIM * PIX];
__device__ float g_tok  [BATCH * NTOK * C_DIM];
__device__ float g_scores[(size_t)BATCH * NTOK * NTOK];
__device__ float g_att  [BATCH * NTOK * C_DIM];

// ---------------- tf32 helpers ----------------
__device__ __forceinline__ uint32_t f2tf32(float x) {
    uint32_t u;
    asm("cvt.rna.tf32.f32 %0, %1;" : "=r"(u) : "f"(x));
    return u;
}

__device__ __forceinline__ void mma8(float* c, const uint32_t* a, const uint32_t* b) {
    asm volatile(
        "mma.sync.aligned.m16n8k8.row.col.f32.tf32.tf32.f32 "
        "{%0,%1,%2,%3},{%4,%5,%6,%7},{%8,%9},{%0,%1,%2,%3};"
        : "+f"(c[0]), "+f"(c[1]), "+f"(c[2]), "+f"(c[3])
        : "r"(a[0]), "r"(a[1]), "r"(a[2]), "r"(a[3]), "r"(b[0]), "r"(b[1]));
}

// ---------------- tf32 GEMM: C = alpha * A * op(B) ----------------
// A: MxK row-major. TB=false: B KxN row-major. TB=true: B NxK row-major.
// 256 threads = 8 warps, warp tile 32x64 (2 x 8 m16n8k8 tiles), BK=16,
// double-buffered smem. All dims must be multiples of tile sizes (they are).
template<int BM, int BN, int WM, int WN, bool TB>
__global__ __launch_bounds__(256, 2)
void gemm_tf32(const float* __restrict__ A, const float* __restrict__ B,
               float* __restrict__ C, int K,
               int lda, int ldb, int ldc, float alpha,
               size_t sA, size_t sB, size_t sC)
{
    constexpr int SA = BM + 8;    // +8 pad: t4*(SA) mod 32 = t4*8 -> conflict-free frag LDS
    constexpr int SB = BN + 8;
    constexpr int NA = BM / 64;   // float4 per thread for A tile
    constexpr int NB = BN / 64;   // float4 per thread for B tile

    __shared__ uint32_t As[2][16 * SA];
    __shared__ uint32_t Bs[2][16 * SB];

    const int bz = blockIdx.z;
    A += (size_t)bz * sA;
    B += (size_t)bz * sB;
    C += (size_t)bz * sC;

    const int row0 = blockIdx.y * BM;
    const int col0 = blockIdx.x * BN;
    const int tid  = threadIdx.x;
    const int lane = tid & 31;
    const int wid  = tid >> 5;
    const int wm   = wid % WM;
    const int wn   = wid / WM;
    const int g    = lane >> 2;
    const int t4   = lane & 3;
    const int arow = wm * (BM / WM);   // 32
    const int bcol = wn * (BN / WN);   // 64

    float acc[2][8][4];
    #pragma unroll
    for (int mi = 0; mi < 2; mi++)
        #pragma unroll
        for (int ni = 0; ni < 8; ni++)
            #pragma unroll
            for (int v = 0; v < 4; v++) acc[mi][ni][v] = 0.f;

    float4 ra[NA], rb[NB];

    auto ldgA = [&](int k0) {
        #pragma unroll
        for (int u = 0; u < NA; u++) {
            int i = tid + u * 256;
            int r = i >> 2, k4 = i & 3;
            ra[u] = *(const float4*)(A + (size_t)(row0 + r) * lda + k0 + k4 * 4);
        }
    };
    auto stsA = [&](int buf) {
        #pragma unroll
        for (int u = 0; u < NA; u++) {
            int i = tid + u * 256;
            int r = i >> 2, k4 = i & 3;
            uint32_t* p = &As[buf][(k4 * 4) * SA + r];
            p[0 * SA] = f2tf32(ra[u].x);
            p[1 * SA] = f2tf32(ra[u].y);
            p[2 * SA] = f2tf32(ra[u].z);
            p[3 * SA] = f2tf32(ra[u].w);
        }
    };
    auto ldgB = [&](int k0) {
        #pragma unroll
        for (int u = 0; u < NB; u++) {
            int i = tid + u * 256;
            if (TB) {
                int n = i >> 2, k4 = i & 3;
                rb[u] = *(const float4*)(B + (size_t)(col0 + n) * ldb + k0 + k4 * 4);
            } else {
                int k = i / (BN / 4), n4 = i % (BN / 4);
                rb[u] = *(const float4*)(B + (size_t)(k0 + k) * ldb + col0 + n4 * 4);
            }
        }
    };
    auto stsB = [&](int buf) {
        #pragma unroll
        for (int u = 0; u < NB; u++) {
            int i = tid + u * 256;
            if (TB) {
                int n = i >> 2, k4 = i & 3;
                uint32_t* p = &Bs[buf][(k4 * 4) * SB + n];
                p[0 * SB] = f2tf32(rb[u].x);
                p[1 * SB] = f2tf32(rb[u].y);
                p[2 * SB] = f2tf32(rb[u].z);
                p[3 * SB] = f2tf32(rb[u].w);
            } else {
                int k = i / (BN / 4), n4 = i % (BN / 4);
                uint4 v;
                v.x = f2tf32(rb[u].x); v.y = f2tf32(rb[u].y);
                v.z = f2tf32(rb[u].z); v.w = f2tf32(rb[u].w);
                *(uint4*)&Bs[buf][k * SB + n4 * 4] = v;
            }
        }
    };

    ldgA(0); ldgB(0);
    stsA(0); stsB(0);
    __syncthreads();

    const int KT = K / 16;
    for (int kt = 0; kt < KT; kt++) {
        int cur = kt & 1, nxt = cur ^ 1;
        if (kt + 1 < KT) { ldgA((kt + 1) * 16); ldgB((kt + 1) * 16); }

        #pragma unroll
        for (int ks = 0; ks < 2; ks++) {
            const int kb = ks * 8;
            uint32_t af[2][4], bf[8][2];
            #pragma unroll
            for (int mi = 0; mi < 2; mi++) {
                int mr = arow + mi * 16 + g;
                af[mi][0] = As[cur][(kb + t4) * SA + mr];
                af[mi][1] = As[cur][(kb + t4) * SA + mr + 8];
                af[mi][2] = As[cur][(kb + t4 + 4) * SA + mr];
                af[mi][3] = As[cur][(kb + t4 + 4) * SA + mr + 8];
            }
            #pragma unroll
            for (int ni = 0; ni < 8; ni++) {
                int nc = bcol + ni * 8 + g;
                bf[ni][0] = Bs[cur][(kb + t4) * SB + nc];
                bf[ni][1] = Bs[cur][(kb + t4 + 4) * SB + nc];
            }
            #pragma unroll
            for (int mi = 0; mi < 2; mi++)
                #pragma unroll
                for (int ni = 0; ni < 8; ni++)
                    mma8(acc[mi][ni], af[mi], bf[ni]);
        }

        if (kt + 1 < KT) { stsA(nxt); stsB(nxt); }
        __syncthreads();
    }

    #pragma unroll
    for (int mi = 0; mi < 2; mi++) {
        int r = row0 + arow + mi * 16 + g;
        #pragma unroll
        for (int ni = 0; ni < 8; ni++) {
            int c = col0 + bcol + ni * 8 + t4 * 2;
            float2 v0, v1;
            v0.x = alpha * acc[mi][ni][0];
            v0.y = alpha * acc[mi][ni][1];
            v1.x = alpha * acc[mi][ni][2];
            v1.y = alpha * acc[mi][ni][3];
            *(float2*)&C[(size_t)r * ldc + c]       = v0;
            *(float2*)&C[(size_t)(r + 8) * ldc + c] = v1;
        }
    }
}

// ---------------- fp32 GEMM (kept for proj / fuse 1x1 convs) ----------------
template<bool TB>
__global__ __launch_bounds__(256)
void gemm128(const float* __restrict__ A, const float* __restrict__ Bm,
             float* __restrict__ Cm,
             int M, int Np, int K, int lda, int ldb, int ldc,
             float alpha, const float* __restrict__ bias,
             size_t sA, size_t sB, size_t sC)
{
    __shared__ float As[8][132];
    __shared__ float Bs[8][132];

    int bz = blockIdx.z;
    A  += (size_t)bz * sA;
    Bm += (size_t)bz * sB;
    Cm += (size_t)bz * sC;

    int tid = threadIdx.x;
    int tx = tid % 16;
    int ty = tid / 16;
    int row0 = blockIdx.y * 128;
    int col0 = blockIdx.x * 128;

    float acc[8][8];
    #pragma unroll
    for (int i = 0; i < 8; i++)
        #pragma unroll
        for (int j = 0; j < 8; j++) acc[i][j] = 0.f;

    int a_k = tid % 8;
    int a_m = (tid / 8) * 4;

    for (int k0 = 0; k0 < K; k0 += 8) {
        #pragma unroll
        for (int j = 0; j < 4; j++) {
            int m = a_m + j;
            int kk = k0 + a_k;
            float v = 0.f;
            if (row0 + m < M && kk < K) v = A[(size_t)(row0 + m) * lda + kk];
            As[a_k][m] = v;
        }
        {
            int b_n  = tid % 128;
            int b_kb = (tid / 128) * 4;
            #pragma unroll
            for (int j = 0; j < 4; j++) {
                int kk = k0 + b_kb + j;
                float v = 0.f;
                if (kk < K && col0 + b_n < Np) v = Bm[(size_t)kk * ldb + col0 + b_n];
                Bs[b_kb + j][b_n] = v;
            }
        }
        __syncthreads();

        #pragma unroll
        for (int kk = 0; kk < 8; kk++) {
            float a[8], b[8];
            #pragma unroll
            for (int i = 0; i < 8; i++) a[i] = As[kk][ty * 8 + i];
            #pragma unroll
            for (int j = 0; j < 8; j++) b[j] = Bs[kk][tx * 8 + j];
            #pragma unroll
            for (int i = 0; i < 8; i++)
                #pragma unroll
                for (int j = 0; j < 8; j++)
                    acc[i][j] += a[i] * b[j];
        }
        __syncthreads();
    }

    #pragma unroll
    for (int i = 0; i < 8; i++) {
        int m = row0 + ty * 8 + i;
        if (m >= M) continue;
        float bv = bias ? bias[m] : 0.f;
        #pragma unroll
        for (int j = 0; j < 8; j++) {
            int n = col0 + tx * 8 + j;
            if (n < Np) Cm[(size_t)m * ldc + n] = alpha * acc[i][j] + bv;
        }
    }
}

// ---------------- reduce ----------------
__global__ __launch_bounds__(256)
void reduce_kernel(const float* __restrict__ fmap, const float* __restrict__ w,
                   const float* __restrict__ bias, float* __restrict__ xr)
{
    __shared__ float ws[INNER * C_DIM];
    int tid = threadIdx.x;
    for (int i = tid; i < INNER * C_DIM; i += 256) ws[i] = w[i];
    __syncthreads();

    int b = blockIdx.y;
    int p = blockIdx.x * 256 + tid;
    const float* fin = fmap + (size_t)b * C_DIM * PIX;
    float acc[INNER];
    #pragma unroll
    for (int o = 0; o < INNER; o++) acc[o] = 0.f;
    for (int ci = 0; ci < C_DIM; ci++) {
        float v = fin[(size_t)ci * PIX + p];
        #pragma unroll
        for (int o = 0; o < INNER; o++) acc[o] += ws[o * C_DIM + ci] * v;
    }
    float* xo = xr + (size_t)b * INNER * PIX;
    #pragma unroll
    for (int o = 0; o < INNER; o++) xo[(size_t)o * PIX + p] = acc[o] + bias[o];
}

// ---------------- dilated 3x3 conv ----------------
__global__ __launch_bounds__(256)
void dilconv_kernel(const float* __restrict__ xr, const float* __restrict__ dw,
                    const float* __restrict__ db, float* __restrict__ conv)
{
    __shared__ float ws[INNER * INNER * 9];
    int i = blockIdx.z;
    int d = i + 1;
    int b = blockIdx.y;
    int tid = threadIdx.x;
    for (int k = tid; k < INNER * INNER * 9; k += 256)
        ws[k] = dw[(size_t)i * INNER * INNER * 9 + k];
    __syncthreads();

    int p = blockIdx.x * 256 + tid;
    int h = p / HW, w = p % HW;
    const float* xin = xr + (size_t)b * INNER * PIX;
    float acc[INNER];
    #pragma unroll
    for (int co = 0; co < INNER; co++) acc[co] = 0.f;

    #pragma unroll
    for (int kh = 0; kh < 3; kh++) {
        int hh = h + (kh - 1) * d;
        if (hh < 0 || hh >= HW) continue;
        #pragma unroll
        for (int kw = 0; kw < 3; kw++) {
            int ww = w + (kw - 1) * d;
            if (ww < 0 || ww >= HW) continue;
            int q = hh * HW + ww;
            for (int ci = 0; ci < INNER; ci++) {
                float v = xin[(size_t)ci * PIX + q];
                int widx = ci * 9 + kh * 3 + kw;
                #pragma unroll
                for (int co = 0; co < INNER; co++)
                    acc[co] += ws[co * (INNER * 9) + widx] * v;
            }
        }
    }
    float* cout = conv + ((size_t)(i * BATCH + b) * INNER) * PIX;
    #pragma unroll
    for (int co = 0; co < INNER; co++)
        cout[(size_t)co * PIX + p] = acc[co] + db[i * INNER + co];
}

// ---------------- feats ----------------
__global__ __launch_bounds__(256)
void feats_kernel(const float* __restrict__ xr, const float* __restrict__ conv,
                  float* __restrict__ feats)
{
    int b = blockIdx.y;
    int p = blockIdx.x * 256 + threadIdx.x;
    int h = p / HW, w = p % HW;
    const float* xin = xr + (size_t)b * INNER * PIX;
    float* fo = feats + (size_t)b * NFEAT * PIX;

    int q[6];
    q[0] = p;
    q[1] = h * HW + (HW - 1 - w);
    q[2] = (HW - 1 - h) * HW + w;
    q[3] = w * HW + (HW - 1 - h);
    q[4] = (HW - 1 - h) * HW + (HW - 1 - w);
    q[5] = (HW - 1 - w) * HW + h;

    for (int c = 0; c < INNER; c++) {
        float cv[3];
        #pragma unroll
        for (int i = 0; i < 3; i++)
            cv[i] = conv[((size_t)(i * BATCH + b) * INNER + c) * PIX + p];
        float tv[6];
        #pragma unroll
        for (int t = 0; t < 6; t++)
            tv[t] = xin[(size_t)c * PIX + q[t]];
        #pragma unroll
        for (int i = 0; i < 3; i++)
            #pragma unroll
            for (int t = 0; t < 6; t++)
                fo[((size_t)((i * 6 + t) * INNER + c)) * PIX + p] = cv[i] * tv[t];
    }
}

// ---------------- transpose ----------------
__global__ __launch_bounds__(256)
void transpose_kernel(const float* __restrict__ src, float* __restrict__ dst)
{
    __shared__ float tile[32][33];
    int b = blockIdx.z;
    int p0 = blockIdx.x * 32, c0 = blockIdx.y * 32;
    const float* s = src + (size_t)b * C_DIM * PIX;
    float* d = dst + (size_t)b * NTOK * C_DIM;
    int tx = threadIdx.x, ty = threadIdx.y;
    #pragma unroll
    for (int j = 0; j < 32; j += 8)
        tile[ty + j][tx] = s[(size_t)(c0 + ty + j) * PIX + p0 + tx];
    __syncthreads();
    #pragma unroll
    for (int j = 0; j < 32; j += 8)
        d[(size_t)(p0 + ty + j) * C_DIM + c0 + tx] = tile[tx][ty + j];
}

// ---------------- softmax ----------------
__global__ __launch_bounds__(256)
void softmax_kernel(float* __restrict__ S)
{
    __shared__ float buf[NTOK];
    __shared__ float red[256];
    size_t base = ((size_t)blockIdx.y * NTOK + blockIdx.x) * NTOK;
    float* row = S + base;
    int tid = threadIdx.x;

    float mx = -1e30f;
    for (int i = tid; i < NTOK; i += 256) { float v = row[i]; buf[i] = v; mx = fmaxf(mx, v); }
    red[tid] = mx; __syncthreads();
    for (int s = 128; s > 0; s >>= 1) { if (tid < s) red[tid] = fmaxf(red[tid], red[tid + s]); __syncthreads(); }
    mx = red[0];
    __syncthreads();

    float sum = 0.f;
    for (int i = tid; i < NTOK; i += 256) { float e = __expf(buf[i] - mx); buf[i] = e; sum += e; }
    red[tid] = sum; __syncthreads();
    for (int s = 128; s > 0; s >>= 1) { if (tid < s) red[tid] += red[tid + s]; __syncthreads(); }
    float inv = 1.f / red[0];

    for (int i = tid; i < NTOK; i += 256) row[i] = buf[i] * inv;
}

// ---------------- final ----------------
__global__ __launch_bounds__(256)
void final_kernel(const float* __restrict__ fmap, const float* __restrict__ att,
                  float* __restrict__ out)
{
    __shared__ float tile[32][33];
    int b = blockIdx.z;
    int p0 = blockIdx.x * 32, c0 = blockIdx.y * 32;
    int tx = threadIdx.x, ty = threadIdx.y;
    const float* a = att + (size_t)b * NTOK * C_DIM;
    #pragma unroll
    for (int j = 0; j < 32; j += 8)
        tile[ty + j][tx] = a[(size_t)(p0 + ty + j) * C_DIM + c0 + tx];
    __syncthreads();
    const float* f = fmap + (size_t)b * C_DIM * PIX;
    float* o = out + (size_t)b * C_DIM * PIX;
    #pragma unroll
    for (int j = 0; j < 32; j += 8) {
        int c = c0 + ty + j, p = p0 + tx;
        o[(size_t)c * PIX + p] = f[(size_t)c * PIX + p] + 0.2f * tile[tx][ty + j];
    }
}

// ---------------- launch ----------------
extern "C" void kernel_launch(void* const* d_in, const int* in_sizes, int n_in,
                              void* d_out, int out_size)
{
    const float* x        = (const float*)d_in[0];
    const float* proj_w   = (const float*)d_in[1];
    const float* proj_b   = (const float*)d_in[2];
    const float* reduce_w = (const float*)d_in[3];
    const float* reduce_b = (const float*)d_in[4];
    const float* dil_w    = (const float*)d_in[5];
    const float* dil_b    = (const float*)d_in[6];
    const float* fuse_w   = (const float*)d_in[7];
    const float* fuse_b   = (const float*)d_in[8];
    float* out = (float*)d_out;

    void *p_fmap, *p_xr, *p_conv, *p_feats, *p_tokT, *p_tok, *p_scores, *p_att;
    cudaGetSymbolAddress(&p_fmap,   g_fmap);
    cudaGetSymbolAddress(&p_xr,     g_xr);
    cudaGetSymbolAddress(&p_conv,   g_conv);
    cudaGetSymbolAddress(&p_feats,  g_feats);
    cudaGetSymbolAddress(&p_tokT,   g_tokT);
    cudaGetSymbolAddress(&p_tok,    g_tok);
    cudaGetSymbolAddress(&p_scores, g_scores);
    cudaGetSymbolAddress(&p_att,    g_att);

    float* fmap   = (float*)p_fmap;
    float* xr     = (float*)p_xr;
    float* conv   = (float*)p_conv;
    float* feats  = (float*)p_feats;
    float* tokT   = (float*)p_tokT;
    float* tok    = (float*)p_tok;
    float* scores = (float*)p_scores;
    float* att    = (float*)p_att;

    // 1) proj 1x1
    gemm128<false><<<dim3(PIX/128, C_DIM/128, BATCH), 256>>>(
        proj_w, x, fmap, C_DIM, PIX, C_DIM, C_DIM, PIX, PIX,
        1.f, proj_b, 0, (size_t)C_DIM*PIX, (size_t)C_DIM*PIX);

    // 2) reduce 1x1
    reduce_kernel<<<dim3(PIX/256, BATCH), 256>>>(fmap, reduce_w, reduce_b, xr);

    // 3) dilated convs
    dilconv_kernel<<<dim3(PIX/256, BATCH, 3), 256>>>(xr, dil_w, dil_b, conv);

    // 4) feats
    feats_kernel<<<dim3(PIX/256, BATCH), 256>>>(xr, conv, feats);

    // 5) fuse 1x1
    gemm128<false><<<dim3(PIX/128, C_DIM/128, BATCH), 256>>>(
        fuse_w, feats, tokT, C_DIM, PIX, NFEAT, NFEAT, PIX, PIX,
        1.f, fuse_b, 0, (size_t)NFEAT*PIX, (size_t)C_DIM*PIX);

    // 6) transpose -> tok (b,p,c)
    transpose_kernel<<<dim3(PIX/32, C_DIM/32, BATCH), dim3(32, 8)>>>(tokT, tok);

    // 7) scores = (tok @ tok^T) / 16  — tf32 tensor cores
    gemm_tf32<128, 128, 4, 2, true><<<dim3(NTOK/128, NTOK/128, BATCH), 256>>>(
        tok, tok, scores, C_DIM, C_DIM, C_DIM, NTOK,
        0.0625f, (size_t)NTOK*C_DIM, (size_t)NTOK*C_DIM, (size_t)NTOK*NTOK);

    // 8) row softmax
    softmax_kernel<<<dim3(NTOK, BATCH), 256>>>(scores);

    // 9) att = scores @ tok — tf32 tensor cores, BN=256 reads scores once
    gemm_tf32<64, 256, 2, 4, false><<<dim3(1, NTOK/64, BATCH), 256>>>(
        scores, tok, att, NTOK, NTOK, C_DIM, C_DIM,
        1.f, (size_t)NTOK*NTOK, (size_t)NTOK*C_DIM, (size_t)NTOK*C_DIM);

    // 10) out = fmap + 0.2 * att^T
    final_kernel<<<dim3(PIX/32, C_DIM/32, BATCH), dim3(32, 8)>>>(fmap, att, out);
}